// round 1
// baseline (speedup 1.0000x reference)
#include <cuda_runtime.h>
#include <math.h>

#define BB 8
#define NN 8192
#define IND 512
#define TD 512
#define NH 8
#define HD 64
#define TM 64          // tokens per block tile
#define SCALE 0.125f   // 64^-0.5

// ---------------- scratch (device globals; no runtime allocation) ----------
__device__ float g_q[(size_t)BB * NN * TD];      // normalized q, 128 MB
__device__ float g_logit[(size_t)BB * NN * NH];  // 2 MB
__device__ float g_G[(size_t)BB * NH * HD];      // 16 KB

// ===========================================================================
// K1: q = l2norm(x @ Wq^T + bq) per head; logits = (q . w_g) * scale
// grid = B * N/64 blocks, 256 threads, dyn smem = 3*(64*65)+128 floats
// ===========================================================================
__global__ void k_qpass(const float* __restrict__ x, const float* __restrict__ Wq,
                        const float* __restrict__ bq, const float* __restrict__ wg)
{
    extern __shared__ float sm[];
    float* Xs   = sm;                 // 64*65
    float* Ws   = Xs + 64 * 65;       // 64*65
    float* Qs   = Ws + 64 * 65;       // 64*65
    float* invs = Qs + 64 * 65;       // 64
    float* wgs  = invs + 64;          // 64

    const int blk = blockIdx.x;
    const int bi  = blk / (NN / TM);
    const int t0  = (blk % (NN / TM)) * TM;
    const int tid = threadIdx.x;
    const int tx  = tid & 15;
    const int ty  = tid >> 4;
    const float* xb = x + ((size_t)bi * NN + t0) * IND;

    for (int c = 0; c < NH; ++c) {
        float acc[4][4];
        #pragma unroll
        for (int i = 0; i < 4; ++i)
            #pragma unroll
            for (int j = 0; j < 4; ++j) acc[i][j] = 0.f;

        if (tid < 64) wgs[tid] = wg[c * HD + tid];

        for (int kt = 0; kt < 8; ++kt) {
            __syncthreads();
            for (int i = tid; i < 4096; i += 256) {
                int r = i >> 6, cc = i & 63;
                Xs[r * 65 + cc] = xb[(size_t)r * IND + kt * 64 + cc];
                Ws[r * 65 + cc] = Wq[(size_t)(c * 64 + r) * IND + kt * 64 + cc];
            }
            __syncthreads();
            #pragma unroll
            for (int kk = 0; kk < 64; ++kk) {
                float a[4], b[4];
                #pragma unroll
                for (int i = 0; i < 4; ++i) a[i] = Xs[(ty * 4 + i) * 65 + kk];
                #pragma unroll
                for (int j = 0; j < 4; ++j) b[j] = Ws[(tx * 4 + j) * 65 + kk];
                #pragma unroll
                for (int i = 0; i < 4; ++i)
                    #pragma unroll
                    for (int j = 0; j < 4; ++j) acc[i][j] += a[i] * b[j];
            }
        }
        __syncthreads();
        #pragma unroll
        for (int i = 0; i < 4; ++i)
            #pragma unroll
            for (int j = 0; j < 4; ++j)
                Qs[(ty * 4 + i) * 65 + tx * 4 + j] = acc[i][j] + bq[c * 64 + tx * 4 + j];
        __syncthreads();
        if (tid < 64) {
            float s = 0.f;
            for (int d = 0; d < 64; ++d) { float v = Qs[tid * 65 + d]; s += v * v; }
            float inv = 1.f / fmaxf(sqrtf(s), 1e-12f);
            invs[tid] = inv;
            float lg = 0.f;
            for (int d = 0; d < 64; ++d) lg += Qs[tid * 65 + d] * wgs[d];
            g_logit[((size_t)bi * NN + t0 + tid) * NH + c] = lg * inv * SCALE;
        }
        __syncthreads();
        for (int i = tid; i < 4096; i += 256) {
            int r = i >> 6, d = i & 63;
            g_q[((size_t)bi * NN + t0 + r) * TD + c * 64 + d] = Qs[r * 65 + d] * invs[r];
        }
    }
}

// ===========================================================================
// K2: per (b,h): softmax over N, G = sum_n A * q.  grid = B*NH, 256 threads
// ===========================================================================
__global__ void k_softmax_g(void)
{
    __shared__ float w[NN];       // 32 KB
    __shared__ float red[256];
    const int b = blockIdx.x / NH;
    const int h = blockIdx.x % NH;
    const int tid = threadIdx.x;

    float m = -1e30f;
    for (int n = tid; n < NN; n += 256) {
        float l = g_logit[((size_t)b * NN + n) * NH + h];
        w[n] = l;
        m = fmaxf(m, l);
    }
    red[tid] = m; __syncthreads();
    for (int s = 128; s > 0; s >>= 1) {
        if (tid < s) red[tid] = fmaxf(red[tid], red[tid + s]);
        __syncthreads();
    }
    m = red[0]; __syncthreads();

    float sum = 0.f;
    for (int n = tid; n < NN; n += 256) {
        float e = expf(w[n] - m);
        w[n] = e;
        sum += e;
    }
    red[tid] = sum; __syncthreads();
    for (int s = 128; s > 0; s >>= 1) {
        if (tid < s) red[tid] += red[tid + s];
        __syncthreads();
    }
    float invsum = 1.f / red[0];
    __syncthreads();

    const int d = tid & 63;
    const int grp = tid >> 6;     // 4 token groups
    float acc = 0.f;
    for (int n = grp; n < NN; n += 4)
        acc += w[n] * g_q[((size_t)b * NN + n) * TD + h * HD + d];
    red[tid] = acc; __syncthreads();
    if (tid < 64) {
        float g = red[tid] + red[tid + 64] + red[tid + 128] + red[tid + 192];
        g_G[((size_t)b * NH + h) * HD + tid] = g * invsum;
    }
}

// ===========================================================================
// K3: fused tail:  k=l2norm(x@Wk^T+bk); U=k*G; H=U@Wp^T+bp+q; out=H@Wf^T+bf
// grid = B*N/64 blocks, 256 threads
// dyn smem floats: Us 64*516 + Xs 64*65 + Ws 64*65 + Gs 512 + invs 64
// ===========================================================================
__global__ void k_outpass(const float* __restrict__ x,  const float* __restrict__ Wk,
                          const float* __restrict__ bk, const float* __restrict__ Wp,
                          const float* __restrict__ bp, const float* __restrict__ Wf,
                          const float* __restrict__ bf, float* __restrict__ out)
{
    extern __shared__ float sm[];
    float* Us   = sm;                 // 64 * 516
    float* Xs   = Us + 64 * 516;      // 64 * 65
    float* Ws   = Xs + 64 * 65;       // 64 * 65
    float* Gs   = Ws + 64 * 65;       // 512
    float* invs = Gs + 512;           // 64

    const int blk = blockIdx.x;
    const int bi  = blk / (NN / TM);
    const int t0  = (blk % (NN / TM)) * TM;
    const int tid = threadIdx.x;
    const int tx  = tid & 15;
    const int ty  = tid >> 4;
    const float* xb = x + ((size_t)bi * NN + t0) * IND;

    for (int i = tid; i < TD; i += 256) Gs[i] = g_G[(size_t)bi * TD + i];

    // ---------------- Stage 1: U = (l2norm(x@Wk^T + bk)) * G -----------------
    for (int c = 0; c < NH; ++c) {
        float acc[4][4];
        #pragma unroll
        for (int i = 0; i < 4; ++i)
            #pragma unroll
            for (int j = 0; j < 4; ++j) acc[i][j] = 0.f;

        for (int kt = 0; kt < 8; ++kt) {
            __syncthreads();
            for (int i = tid; i < 4096; i += 256) {
                int r = i >> 6, cc = i & 63;
                Xs[r * 65 + cc] = xb[(size_t)r * IND + kt * 64 + cc];
                Ws[r * 65 + cc] = Wk[(size_t)(c * 64 + r) * IND + kt * 64 + cc];
            }
            __syncthreads();
            #pragma unroll
            for (int kk = 0; kk < 64; ++kk) {
                float a[4], b[4];
                #pragma unroll
                for (int i = 0; i < 4; ++i) a[i] = Xs[(ty * 4 + i) * 65 + kk];
                #pragma unroll
                for (int j = 0; j < 4; ++j) b[j] = Ws[(tx * 4 + j) * 65 + kk];
                #pragma unroll
                for (int i = 0; i < 4; ++i)
                    #pragma unroll
                    for (int j = 0; j < 4; ++j) acc[i][j] += a[i] * b[j];
            }
        }
        __syncthreads();
        #pragma unroll
        for (int i = 0; i < 4; ++i)
            #pragma unroll
            for (int j = 0; j < 4; ++j)
                Xs[(ty * 4 + i) * 65 + tx * 4 + j] = acc[i][j] + bk[c * 64 + tx * 4 + j];
        __syncthreads();
        if (tid < 64) {
            float s = 0.f;
            for (int d = 0; d < 64; ++d) { float v = Xs[tid * 65 + d]; s += v * v; }
            invs[tid] = 1.f / fmaxf(sqrtf(s), 1e-12f);
        }
        __syncthreads();
        for (int i = tid; i < 4096; i += 256) {
            int r = i >> 6, d = i & 63;
            Us[r * 516 + c * 64 + d] = Xs[r * 65 + d] * invs[r] * Gs[c * 64 + d];
        }
    }

    // ------------- Stage 2+3: H = U@Wp^T + bp + q ; out = H@Wf^T + bf --------
    float oacc[4][4];
    #pragma unroll
    for (int i = 0; i < 4; ++i)
        #pragma unroll
        for (int j = 0; j < 4; ++j) oacc[i][j] = 0.f;

    for (int c = 0; c < NH; ++c) {
        float hacc[4][4];
        #pragma unroll
        for (int i = 0; i < 4; ++i)
            #pragma unroll
            for (int j = 0; j < 4; ++j) hacc[i][j] = 0.f;

        for (int kt = 0; kt < 8; ++kt) {
            __syncthreads();
            for (int i = tid; i < 4096; i += 256) {
                int r = i >> 6, cc = i & 63;
                Ws[r * 65 + cc] = Wp[(size_t)(c * 64 + r) * TD + kt * 64 + cc];
            }
            __syncthreads();
            #pragma unroll
            for (int kk = 0; kk < 64; ++kk) {
                float a[4], b[4];
                #pragma unroll
                for (int i = 0; i < 4; ++i) a[i] = Us[(ty * 4 + i) * 516 + kt * 64 + kk];
                #pragma unroll
                for (int j = 0; j < 4; ++j) b[j] = Ws[(tx * 4 + j) * 65 + kk];
                #pragma unroll
                for (int i = 0; i < 4; ++i)
                    #pragma unroll
                    for (int j = 0; j < 4; ++j) hacc[i][j] += a[i] * b[j];
            }
        }
        // + bp + q (residual); stage q tile via Xs (coalesced)
        __syncthreads();
        for (int i = tid; i < 4096; i += 256) {
            int r = i >> 6, cc = i & 63;
            Xs[r * 65 + cc] = g_q[((size_t)bi * NN + t0 + r) * TD + c * 64 + cc];
        }
        __syncthreads();
        #pragma unroll
        for (int i = 0; i < 4; ++i)
            #pragma unroll
            for (int j = 0; j < 4; ++j)
                hacc[i][j] += bp[c * 64 + tx * 4 + j] + Xs[(ty * 4 + i) * 65 + tx * 4 + j];
        // stage H chunk to smem, fold into out accumulation with Wf chunk
        __syncthreads();
        #pragma unroll
        for (int i = 0; i < 4; ++i)
            #pragma unroll
            for (int j = 0; j < 4; ++j)
                Xs[(ty * 4 + i) * 65 + tx * 4 + j] = hacc[i][j];
        for (int i = tid; i < 4096; i += 256) {
            int r = i >> 6, cc = i & 63;
            Ws[r * 65 + cc] = Wf[(size_t)r * TD + c * 64 + cc];   // Wf is 64x512
        }
        __syncthreads();
        #pragma unroll
        for (int kk = 0; kk < 64; ++kk) {
            float a[4], b[4];
            #pragma unroll
            for (int i = 0; i < 4; ++i) a[i] = Xs[(ty * 4 + i) * 65 + kk];
            #pragma unroll
            for (int j = 0; j < 4; ++j) b[j] = Ws[(tx * 4 + j) * 65 + kk];
            #pragma unroll
            for (int i = 0; i < 4; ++i)
                #pragma unroll
                for (int j = 0; j < 4; ++j) oacc[i][j] += a[i] * b[j];
        }
        __syncthreads();
    }

    #pragma unroll
    for (int i = 0; i < 4; ++i)
        #pragma unroll
        for (int j = 0; j < 4; ++j)
            out[((size_t)bi * NN + t0 + ty * 4 + i) * HD + tx * 4 + j] =
                oacc[i][j] + bf[tx * 4 + j];
}

// ===========================================================================
extern "C" void kernel_launch(void* const* d_in, const int* in_sizes, int n_in,
                              void* d_out, int out_size)
{
    (void)in_sizes; (void)n_in; (void)out_size;
    const float* x  = (const float*)d_in[0];
    const float* Wq = (const float*)d_in[1];
    const float* bq = (const float*)d_in[2];
    const float* Wk = (const float*)d_in[3];
    const float* bk = (const float*)d_in[4];
    const float* wg = (const float*)d_in[5];
    const float* Wp = (const float*)d_in[6];
    const float* bp = (const float*)d_in[7];
    const float* Wf = (const float*)d_in[8];
    const float* bf = (const float*)d_in[9];
    float* out = (float*)d_out;

    const int grid = BB * (NN / TM);   // 1024
    const int smem_q   = (3 * 64 * 65 + 128) * (int)sizeof(float);                 // ~50.4 KB
    const int smem_out = (64 * 516 + 2 * 64 * 65 + 512 + 64) * (int)sizeof(float); // ~167.7 KB

    cudaFuncSetAttribute(k_qpass,   cudaFuncAttributeMaxDynamicSharedMemorySize, smem_q);
    cudaFuncSetAttribute(k_outpass, cudaFuncAttributeMaxDynamicSharedMemorySize, smem_out);

    k_qpass<<<grid, 256, smem_q>>>(x, Wq, bq, wg);
    k_softmax_g<<<BB * NH, 256>>>();
    k_outpass<<<grid, 256, smem_out>>>(x, Wk, bk, Wp, bp, Wf, bf, out);
}

// round 5
// speedup vs baseline: 4.6934x; 4.6934x over previous
#include <cuda_runtime.h>
#include <math.h>

#define BB 8
#define NN 8192
#define IND 512
#define TD 512
#define NH 8
#define SCALE 0.125f

// ---------------- scratch (device globals; no runtime allocation) ----------
__device__ float g_q[(size_t)BB * NN * TD];        // normalized q   128MB
__device__ float g_u[(size_t)BB * NN * TD];        // U = k_norm*G   128MB
__device__ float g_logit[(size_t)BB * NH * NN];    // [b][h][n]
__device__ float g_ms[BB * NH * 2];                // (max, 1/sum)
__device__ float g_G[BB * TD];
__device__ float g_wc[64 * 1024];                  // [Wf@Wp | Wf], tf32-rounded
__device__ float g_bc[64];                         // Wf@bp + bf

// ---------------- helpers ---------------------------------------------------
__device__ __forceinline__ float tf32rn(float v) {
    unsigned u;
    asm("cvt.rna.tf32.f32 %0, %1;" : "=r"(u) : "f"(v));
    return __uint_as_float(u);
}

#define MMA8(d, a, b)                                                          \
    asm volatile(                                                              \
        "mma.sync.aligned.m16n8k8.row.col.f32.tf32.tf32.f32 "                  \
        "{%0,%1,%2,%3},{%4,%5,%6,%7},{%8,%9},{%0,%1,%2,%3};"                   \
        : "+f"((d)[0]), "+f"((d)[1]), "+f"((d)[2]), "+f"((d)[3])               \
        : "r"((a)[0]), "r"((a)[1]), "r"((a)[2]), "r"((a)[3]),                  \
          "r"((b)[0]), "r"((b)[1]))

#define LDST 36   // smem row stride in words (conflict-free: (4g+c)%32 distinct)

// ===========================================================================
// K0: Wc = [Wf@Wp | Wf] (tf32-rounded), bc = Wf@bp + bf.   grid 64, 512 thr
// ===========================================================================
__global__ void k_wc(const float* __restrict__ Wp, const float* __restrict__ Wf,
                     const float* __restrict__ bp, const float* __restrict__ bf)
{
    __shared__ float wf[512];
    __shared__ float red[512];
    const int r = blockIdx.x, tid = threadIdx.x;
    wf[tid] = Wf[(size_t)r * 512 + tid];
    __syncthreads();
    float acc = 0.f;
    for (int k = 0; k < 512; ++k) acc += wf[k] * Wp[(size_t)k * 512 + tid];
    g_wc[(size_t)r * 1024 + tid] = tf32rn(acc);
    g_wc[(size_t)r * 1024 + 512 + tid] = tf32rn(wf[tid]);
    red[tid] = wf[tid] * bp[tid];
    __syncthreads();
    for (int s = 256; s > 0; s >>= 1) {
        if (tid < s) red[tid] += red[tid + s];
        __syncthreads();
    }
    if (tid == 0) g_bc[r] = red[0] + bf[r];
}

// ===========================================================================
// K1/K3a: tensor GEMM tile [128 tok x 128 cols], K=512, tf32 mma.sync.
//   mode 0: +bq, l2norm, logits -> g_q, g_logit
//   mode 1: +bk, l2norm, *G     -> g_u
// grid = B * 64 token-tiles * 4 col-chunks = 2048, 256 threads
// ===========================================================================
__global__ void __launch_bounds__(256, 2)
k_proj(const float* __restrict__ x, const float* __restrict__ W,
       const float* __restrict__ bias, const float* __restrict__ wg, int mode)
{
    extern __shared__ float sm[];
    float* Xh = sm;                    // [128][36]
    float* Xl = Xh + 128 * LDST;       // [128][36]
    float* Ws = Xl + 128 * LDST;       // [128][36]

    const int tid  = threadIdx.x;
    const int wid  = tid >> 5, lane = tid & 31;
    const int grp  = lane >> 2, tig = lane & 3;
    const int wr   = wid & 3,  wc  = wid >> 2;

    const int bx  = blockIdx.x;
    const int bi  = bx >> 8;
    const int rem = bx & 255;
    const int nb  = rem & 3;           // col chunk (fastest: L2 reuse of X)
    const int t0  = (rem >> 2) << 7;   // token tile base

    const float* xb = x + ((size_t)bi * NN + t0) * IND;
    const float* Wb = W + (size_t)(nb * 128) * IND;

    float acc[2][8][4];
    #pragma unroll
    for (int mt = 0; mt < 2; ++mt)
        #pragma unroll
        for (int nt = 0; nt < 8; ++nt)
            #pragma unroll
            for (int j = 0; j < 4; ++j) acc[mt][nt][j] = 0.f;

    for (int kt = 0; kt < 16; ++kt) {
        __syncthreads();
        #pragma unroll
        for (int i = 0; i < 4; ++i) {            // X chunk [128,32] -> hi/lo
            int e = tid + i * 256;
            int r = e >> 3, c4 = e & 7;
            float4 v = *(const float4*)(xb + (size_t)r * IND + kt * 32 + c4 * 4);
            float4 h, l;
            h.x = tf32rn(v.x); l.x = tf32rn(v.x - h.x);
            h.y = tf32rn(v.y); l.y = tf32rn(v.y - h.y);
            h.z = tf32rn(v.z); l.z = tf32rn(v.z - h.z);
            h.w = tf32rn(v.w); l.w = tf32rn(v.w - h.w);
            *(float4*)(Xh + r * LDST + c4 * 4) = h;
            *(float4*)(Xl + r * LDST + c4 * 4) = l;
        }
        #pragma unroll
        for (int i = 0; i < 4; ++i) {            // W chunk [128,32], RN-tf32
            int e = tid + i * 256;
            int r = e >> 3, c4 = e & 7;
            float4 v = *(const float4*)(Wb + (size_t)r * IND + kt * 32 + c4 * 4);
            v.x = tf32rn(v.x); v.y = tf32rn(v.y);
            v.z = tf32rn(v.z); v.w = tf32rn(v.w);
            *(float4*)(Ws + r * LDST + c4 * 4) = v;
        }
        __syncthreads();

        #pragma unroll
        for (int ks = 0; ks < 4; ++ks) {
            const int kb = ks * 8;
            unsigned ah[2][4], al[2][4], bfr[8][2];
            #pragma unroll
            for (int mt = 0; mt < 2; ++mt) {
                const int r0 = wr * 32 + mt * 16 + grp;
                ah[mt][0] = __float_as_uint(Xh[r0 * LDST + kb + tig]);
                ah[mt][1] = __float_as_uint(Xh[(r0 + 8) * LDST + kb + tig]);
                ah[mt][2] = __float_as_uint(Xh[r0 * LDST + kb + tig + 4]);
                ah[mt][3] = __float_as_uint(Xh[(r0 + 8) * LDST + kb + tig + 4]);
                al[mt][0] = __float_as_uint(Xl[r0 * LDST + kb + tig]);
                al[mt][1] = __float_as_uint(Xl[(r0 + 8) * LDST + kb + tig]);
                al[mt][2] = __float_as_uint(Xl[r0 * LDST + kb + tig + 4]);
                al[mt][3] = __float_as_uint(Xl[(r0 + 8) * LDST + kb + tig + 4]);
            }
            #pragma unroll
            for (int nt = 0; nt < 8; ++nt) {
                const int c0 = wc * 64 + nt * 8 + grp;
                bfr[nt][0] = __float_as_uint(Ws[c0 * LDST + kb + tig]);
                bfr[nt][1] = __float_as_uint(Ws[c0 * LDST + kb + tig + 4]);
            }
            #pragma unroll
            for (int mt = 0; mt < 2; ++mt)
                #pragma unroll
                for (int nt = 0; nt < 8; ++nt) {
                    MMA8(acc[mt][nt], ah[mt], bfr[nt]);
                    MMA8(acc[mt][nt], al[mt], bfr[nt]);
                }
        }
    }

    // ---------------- epilogue: bias, l2norm, logits / *G --------------------
    const int ghead = nb * 2 + wc;
    float* base = (mode == 0 ? g_q : g_u);
    #pragma unroll
    for (int mt = 0; mt < 2; ++mt)
        #pragma unroll
        for (int s = 0; s < 2; ++s) {
            const int row = wr * 32 + mt * 16 + s * 8 + grp;
            const int token = t0 + row;
            float v[16];
            float ss = 0.f;
            #pragma unroll
            for (int nt = 0; nt < 8; ++nt)
                #pragma unroll
                for (int j = 0; j < 2; ++j) {
                    const int cih = nt * 8 + tig * 2 + j;
                    float val = acc[mt][nt][s * 2 + j] + bias[ghead * 64 + cih];
                    v[nt * 2 + j] = val;
                    ss += val * val;
                }
            ss += __shfl_xor_sync(0xFFFFFFFFu, ss, 1);
            ss += __shfl_xor_sync(0xFFFFFFFFu, ss, 2);
            const float inv = 1.f / fmaxf(sqrtf(ss), 1e-12f);
            if (mode == 0) {
                float lg = 0.f;
                #pragma unroll
                for (int nt = 0; nt < 8; ++nt)
                    #pragma unroll
                    for (int j = 0; j < 2; ++j)
                        lg += v[nt * 2 + j] * wg[ghead * 64 + nt * 8 + tig * 2 + j];
                lg += __shfl_xor_sync(0xFFFFFFFFu, lg, 1);
                lg += __shfl_xor_sync(0xFFFFFFFFu, lg, 2);
                if (tig == 0)
                    g_logit[((size_t)(bi * NH + ghead)) * NN + token] = lg * inv * SCALE;
                #pragma unroll
                for (int j = 0; j < 16; ++j) v[j] *= inv;
            } else {
                #pragma unroll
                for (int nt = 0; nt < 8; ++nt)
                    #pragma unroll
                    for (int j = 0; j < 2; ++j)
                        v[nt * 2 + j] *= inv * g_G[bi * TD + ghead * 64 + nt * 8 + tig * 2 + j];
            }
            float* dst = base + ((size_t)bi * NN + token) * TD + ghead * 64;
            #pragma unroll
            for (int nt = 0; nt < 8; ++nt)
                *(float2*)(dst + nt * 8 + tig * 2) = make_float2(v[nt * 2], v[nt * 2 + 1]);
        }
}

// ===========================================================================
// K2a: softmax stats per (b,h) + zero G.  grid 64, 256 threads
// ===========================================================================
__global__ void k_stats(void)
{
    __shared__ float red[256];
    const int b = blockIdx.x >> 3, h = blockIdx.x & 7, tid = threadIdx.x;
    const float* L = g_logit + ((size_t)(b * NH + h)) * NN;
    float m = -1e30f;
    for (int n = tid; n < NN; n += 256) m = fmaxf(m, L[n]);
    red[tid] = m; __syncthreads();
    for (int s = 128; s > 0; s >>= 1) {
        if (tid < s) red[tid] = fmaxf(red[tid], red[tid + s]);
        __syncthreads();
    }
    m = red[0]; __syncthreads();
    float sum = 0.f;
    for (int n = tid; n < NN; n += 256) sum += expf(L[n] - m);
    red[tid] = sum; __syncthreads();
    for (int s = 128; s > 0; s >>= 1) {
        if (tid < s) red[tid] += red[tid + s];
        __syncthreads();
    }
    if (tid == 0) {
        g_ms[(b * NH + h) * 2] = m;
        g_ms[(b * NH + h) * 2 + 1] = 1.f / red[0];
    }
    if (tid < 64) g_G[b * TD + h * 64 + tid] = 0.f;
}

// ===========================================================================
// K2b: G accumulation.  grid 256 (b x 32 chunks of 256 tokens), 256 threads
// ===========================================================================
__global__ void __launch_bounds__(256) k_accG(void)
{
    __shared__ float ws[8 * 256];
    __shared__ float ms[16];
    const int b = blockIdx.x >> 5, n0 = (blockIdx.x & 31) * 256, tid = threadIdx.x;
    if (tid < 16) ms[tid] = g_ms[b * 16 + tid];
    __syncthreads();
    for (int i = tid; i < 2048; i += 256) {
        int h = i >> 8, t = i & 255;
        ws[i] = expf(g_logit[((size_t)(b * NH + h)) * NN + n0 + t] - ms[h * 2]) * ms[h * 2 + 1];
    }
    __syncthreads();
    const int d0 = tid, d1 = tid + 256;
    const int h0 = d0 >> 6, h1 = d1 >> 6;
    float a0 = 0.f, a1 = 0.f;
    const float* qb = g_q + ((size_t)b * NN + n0) * TD;
    for (int t = 0; t < 256; ++t) {
        a0 += ws[h0 * 256 + t] * qb[(size_t)t * TD + d0];
        a1 += ws[h1 * 256 + t] * qb[(size_t)t * TD + d1];
    }
    atomicAdd(&g_G[b * TD + d0], a0);
    atomicAdd(&g_G[b * TD + d1], a1);
}

// ===========================================================================
// K3b: out = [U|q] @ Wc^T + bc  (M=128, N=64, K=1024). grid 512, 256 threads
// ===========================================================================
__global__ void __launch_bounds__(256, 2) k_out(float* __restrict__ out)
{
    extern __shared__ float sm[];
    float* Ah = sm;                    // [128][36]
    float* Al = Ah + 128 * LDST;
    float* Bs = Al + 128 * LDST;       // [64][36]

    const int tid  = threadIdx.x;
    const int wid  = tid >> 5, lane = tid & 31;
    const int grp  = lane >> 2, tig = lane & 3;
    const int bi   = blockIdx.x >> 6;
    const int t0   = (blockIdx.x & 63) << 7;

    float acc[8][4];
    #pragma unroll
    for (int nt = 0; nt < 8; ++nt)
        #pragma unroll
        for (int j = 0; j < 4; ++j) acc[nt][j] = 0.f;

    for (int kt = 0; kt < 32; ++kt) {
        const float* A = (kt < 16 ? g_u : g_q) + ((size_t)bi * NN + t0) * TD + (kt & 15) * 32;
        __syncthreads();
        #pragma unroll
        for (int i = 0; i < 4; ++i) {
            int e = tid + i * 256;
            int r = e >> 3, c4 = e & 7;
            float4 v = *(const float4*)(A + (size_t)r * TD + c4 * 4);
            float4 h, l;
            h.x = tf32rn(v.x); l.x = tf32rn(v.x - h.x);
            h.y = tf32rn(v.y); l.y = tf32rn(v.y - h.y);
            h.z = tf32rn(v.z); l.z = tf32rn(v.z - h.z);
            h.w = tf32rn(v.w); l.w = tf32rn(v.w - h.w);
            *(float4*)(Ah + r * LDST + c4 * 4) = h;
            *(float4*)(Al + r * LDST + c4 * 4) = l;
        }
        #pragma unroll
        for (int i = 0; i < 2; ++i) {            // B chunk [64,32], pre-rounded
            int e = tid + i * 256;
            int r = e >> 3, c4 = e & 7;
            float4 v = *(const float4*)(g_wc + (size_t)r * 1024 + kt * 32 + c4 * 4);
            *(float4*)(Bs + r * LDST + c4 * 4) = v;
        }
        __syncthreads();

        #pragma unroll
        for (int ks = 0; ks < 4; ++ks) {
            const int kb = ks * 8;
            unsigned ah[4], al[4], bfr[8][2];
            const int r0 = wid * 16 + grp;
            ah[0] = __float_as_uint(Ah[r0 * LDST + kb + tig]);
            ah[1] = __float_as_uint(Ah[(r0 + 8) * LDST + kb + tig]);
            ah[2] = __float_as_uint(Ah[r0 * LDST + kb + tig + 4]);
            ah[3] = __float_as_uint(Ah[(r0 + 8) * LDST + kb + tig + 4]);
            al[0] = __float_as_uint(Al[r0 * LDST + kb + tig]);
            al[1] = __float_as_uint(Al[(r0 + 8) * LDST + kb + tig]);
            al[2] = __float_as_uint(Al[r0 * LDST + kb + tig + 4]);
            al[3] = __float_as_uint(Al[(r0 + 8) * LDST + kb + tig + 4]);
            #pragma unroll
            for (int nt = 0; nt < 8; ++nt) {
                const int c0 = nt * 8 + grp;
                bfr[nt][0] = __float_as_uint(Bs[c0 * LDST + kb + tig]);
                bfr[nt][1] = __float_as_uint(Bs[c0 * LDST + kb + tig + 4]);
            }
            #pragma unroll
            for (int nt = 0; nt < 8; ++nt) {
                MMA8(acc[nt], ah, bfr[nt]);
                MMA8(acc[nt], al, bfr[nt]);
            }
        }
    }

    #pragma unroll
    for (int s = 0; s < 2; ++s) {
        const int row = wid * 16 + s * 8 + grp;
        const int token = t0 + row;
        float* orow = out + ((size_t)bi * NN + token) * 64;
        #pragma unroll
        for (int nt = 0; nt < 8; ++nt) {
            const int c = nt * 8 + tig * 2;
            float2 v = make_float2(acc[nt][s * 2] + g_bc[c],
                                   acc[nt][s * 2 + 1] + g_bc[c + 1]);
            *(float2*)(orow + c) = v;
        }
    }
}

// ===========================================================================
extern "C" void kernel_launch(void* const* d_in, const int* in_sizes, int n_in,
                              void* d_out, int out_size)
{
    (void)in_sizes; (void)n_in; (void)out_size;
    const float* x  = (const float*)d_in[0];
    const float* Wq = (const float*)d_in[1];
    const float* bq = (const float*)d_in[2];
    const float* Wk = (const float*)d_in[3];
    const float* bk = (const float*)d_in[4];
    const float* wg = (const float*)d_in[5];
    const float* Wp = (const float*)d_in[6];
    const float* bp = (const float*)d_in[7];
    const float* Wf = (const float*)d_in[8];
    const float* bf = (const float*)d_in[9];
    float* out = (float*)d_out;

    const int smem_proj = 3 * 128 * LDST * (int)sizeof(float);              // 55296
    const int smem_out  = (2 * 128 + 64) * LDST * (int)sizeof(float);       // 46080
    cudaFuncSetAttribute(k_proj, cudaFuncAttributeMaxDynamicSharedMemorySize, smem_proj);
    cudaFuncSetAttribute(k_out,  cudaFuncAttributeMaxDynamicSharedMemorySize, smem_out);

    k_wc<<<64, 512>>>(Wp, Wf, bp, bf);
    k_proj<<<2048, 256, smem_proj>>>(x, Wq, bq, wg, 0);
    k_stats<<<64, 256>>>();
    k_accG<<<256, 256>>>();
    k_proj<<<2048, 256, smem_proj>>>(x, Wk, bk, wg, 1);
    k_out<<<512, 256, smem_out>>>(out);
}

// round 6
// speedup vs baseline: 6.4240x; 1.3687x over previous
#include <cuda_runtime.h>
#include <math.h>

#define BB 8
#define NN 8192
#define IND 512
#define TD 512
#define NH 8
#define SCALE 0.125f

// ---------------- scratch (device globals; no runtime allocation) ----------
__device__ float g_q[(size_t)BB * NN * TD];        // normalized q   128MB
__device__ float g_u[(size_t)BB * NN * TD];        // U = k_norm*G   128MB
__device__ float g_logit[(size_t)BB * NH * NN];    // [b][h][n]
__device__ float g_ms[BB * NH * 2];                // (max, 1/sum)
__device__ float g_G[BB * TD];
__device__ float g_wc[64 * 1024];                  // [Wf@Wp | Wf], tf32-rounded
__device__ float g_bc[64];                         // Wf@bp + bf

// ---------------- helpers ---------------------------------------------------
__device__ __forceinline__ float tf32rn(float v) {
    unsigned u;
    asm("cvt.rna.tf32.f32 %0, %1;" : "=r"(u) : "f"(v));
    return __uint_as_float(u);
}

#define MMA8(d, a, b)                                                          \
    asm volatile(                                                              \
        "mma.sync.aligned.m16n8k8.row.col.f32.tf32.tf32.f32 "                  \
        "{%0,%1,%2,%3},{%4,%5,%6,%7},{%8,%9},{%0,%1,%2,%3};"                   \
        : "+f"((d)[0]), "+f"((d)[1]), "+f"((d)[2]), "+f"((d)[3])               \
        : "r"((a)[0]), "r"((a)[1]), "r"((a)[2]), "r"((a)[3]),                  \
          "r"((b)[0]), "r"((b)[1]))

#define LDST 36   // smem row stride in words (conflict-free)

// ===========================================================================
// K0: Wc = [Wf@Wp | Wf] (tf32-rounded), bc = Wf@bp + bf.   grid 64, 512 thr
// ===========================================================================
__global__ void k_wc(const float* __restrict__ Wp, const float* __restrict__ Wf,
                     const float* __restrict__ bp, const float* __restrict__ bf)
{
    __shared__ float wf[512];
    __shared__ float red[512];
    const int r = blockIdx.x, tid = threadIdx.x;
    wf[tid] = Wf[(size_t)r * 512 + tid];
    __syncthreads();
    float acc = 0.f;
    for (int k = 0; k < 512; ++k) acc += wf[k] * Wp[(size_t)k * 512 + tid];
    g_wc[(size_t)r * 1024 + tid] = tf32rn(acc);
    g_wc[(size_t)r * 1024 + 512 + tid] = tf32rn(wf[tid]);
    red[tid] = wf[tid] * bp[tid];
    __syncthreads();
    for (int s = 256; s > 0; s >>= 1) {
        if (tid < s) red[tid] += red[tid + s];
        __syncthreads();
    }
    if (tid == 0) g_bc[r] = red[0] + bf[r];
}

// ===========================================================================
// K1/K3a: tensor GEMM tile [128 tok x 128 cols], K=512, tf32 mma.sync.
//   mode 0: +bq, l2norm, logits -> g_q, g_logit
//   mode 1: +bk, l2norm, *G     -> g_u
// grid = B * 64 token-tiles * 4 col-chunks = 2048, 256 threads
// ===========================================================================
__global__ void __launch_bounds__(256, 2)
k_proj(const float* __restrict__ x, const float* __restrict__ W,
       const float* __restrict__ bias, const float* __restrict__ wg, int mode)
{
    extern __shared__ float sm[];
    float* Xh = sm;                    // [128][36]
    float* Ws = Xh + 128 * LDST;       // [128][36]

    const int tid  = threadIdx.x;
    const int wid  = tid >> 5, lane = tid & 31;
    const int grp  = lane >> 2, tig = lane & 3;
    const int wr   = wid & 3,  wc  = wid >> 2;

    const int bx  = blockIdx.x;
    const int bi  = bx >> 8;
    const int rem = bx & 255;
    const int nb  = rem & 3;           // col chunk (fastest: L2 reuse of X)
    const int t0  = (rem >> 2) << 7;   // token tile base

    const float* xb = x + ((size_t)bi * NN + t0) * IND;
    const float* Wb = W + (size_t)(nb * 128) * IND;

    float acc[2][8][4];
    #pragma unroll
    for (int mt = 0; mt < 2; ++mt)
        #pragma unroll
        for (int nt = 0; nt < 8; ++nt)
            #pragma unroll
            for (int j = 0; j < 4; ++j) acc[mt][nt][j] = 0.f;

    for (int kt = 0; kt < 16; ++kt) {
        __syncthreads();
        #pragma unroll
        for (int i = 0; i < 4; ++i) {            // X chunk [128,32] RN-tf32
            int e = tid + i * 256;
            int r = e >> 3, c4 = e & 7;
            float4 v = *(const float4*)(xb + (size_t)r * IND + kt * 32 + c4 * 4);
            v.x = tf32rn(v.x); v.y = tf32rn(v.y);
            v.z = tf32rn(v.z); v.w = tf32rn(v.w);
            *(float4*)(Xh + r * LDST + c4 * 4) = v;
        }
        #pragma unroll
        for (int i = 0; i < 4; ++i) {            // W chunk [128,32] RN-tf32
            int e = tid + i * 256;
            int r = e >> 3, c4 = e & 7;
            float4 v = *(const float4*)(Wb + (size_t)r * IND + kt * 32 + c4 * 4);
            v.x = tf32rn(v.x); v.y = tf32rn(v.y);
            v.z = tf32rn(v.z); v.w = tf32rn(v.w);
            *(float4*)(Ws + r * LDST + c4 * 4) = v;
        }
        __syncthreads();

        #pragma unroll
        for (int ks = 0; ks < 4; ++ks) {
            const int kb = ks * 8;
            unsigned ah[2][4], bfr[8][2];
            #pragma unroll
            for (int mt = 0; mt < 2; ++mt) {
                const int r0 = wr * 32 + mt * 16 + grp;
                ah[mt][0] = __float_as_uint(Xh[r0 * LDST + kb + tig]);
                ah[mt][1] = __float_as_uint(Xh[(r0 + 8) * LDST + kb + tig]);
                ah[mt][2] = __float_as_uint(Xh[r0 * LDST + kb + tig + 4]);
                ah[mt][3] = __float_as_uint(Xh[(r0 + 8) * LDST + kb + tig + 4]);
            }
            #pragma unroll
            for (int nt = 0; nt < 8; ++nt) {
                const int c0 = wc * 64 + nt * 8 + grp;
                bfr[nt][0] = __float_as_uint(Ws[c0 * LDST + kb + tig]);
                bfr[nt][1] = __float_as_uint(Ws[c0 * LDST + kb + tig + 4]);
            }
            #pragma unroll
            for (int mt = 0; mt < 2; ++mt)
                #pragma unroll
                for (int nt = 0; nt < 8; ++nt)
                    MMA8(acc[mt][nt], ah[mt], bfr[nt]);
        }
    }

    // ---------------- epilogue: bias, l2norm, logits / *G --------------------
    const int ghead = nb * 2 + wc;
    float* base = (mode == 0 ? g_q : g_u);
    #pragma unroll
    for (int mt = 0; mt < 2; ++mt)
        #pragma unroll
        for (int s = 0; s < 2; ++s) {
            const int row = wr * 32 + mt * 16 + s * 8 + grp;
            const int token = t0 + row;
            float v[16];
            float ss = 0.f;
            #pragma unroll
            for (int nt = 0; nt < 8; ++nt)
                #pragma unroll
                for (int j = 0; j < 2; ++j) {
                    const int cih = nt * 8 + tig * 2 + j;
                    float val = acc[mt][nt][s * 2 + j] + bias[ghead * 64 + cih];
                    v[nt * 2 + j] = val;
                    ss += val * val;
                }
            ss += __shfl_xor_sync(0xFFFFFFFFu, ss, 1);
            ss += __shfl_xor_sync(0xFFFFFFFFu, ss, 2);
            const float inv = 1.f / fmaxf(sqrtf(ss), 1e-12f);
            if (mode == 0) {
                float lg = 0.f;
                #pragma unroll
                for (int nt = 0; nt < 8; ++nt)
                    #pragma unroll
                    for (int j = 0; j < 2; ++j)
                        lg += v[nt * 2 + j] * wg[ghead * 64 + nt * 8 + tig * 2 + j];
                lg += __shfl_xor_sync(0xFFFFFFFFu, lg, 1);
                lg += __shfl_xor_sync(0xFFFFFFFFu, lg, 2);
                if (tig == 0)
                    g_logit[((size_t)(bi * NH + ghead)) * NN + token] = lg * inv * SCALE;
                #pragma unroll
                for (int j = 0; j < 16; ++j) v[j] *= inv;
            } else {
                #pragma unroll
                for (int nt = 0; nt < 8; ++nt)
                    #pragma unroll
                    for (int j = 0; j < 2; ++j)
                        v[nt * 2 + j] *= inv * g_G[bi * TD + ghead * 64 + nt * 8 + tig * 2 + j];
            }
            float* dst = base + ((size_t)bi * NN + token) * TD + ghead * 64;
            #pragma unroll
            for (int nt = 0; nt < 8; ++nt)
                *(float2*)(dst + nt * 8 + tig * 2) = make_float2(v[nt * 2], v[nt * 2 + 1]);
        }
}

// ===========================================================================
// K2a: softmax stats per (b,h) + zero G.  grid 64, 256 threads
// ===========================================================================
__global__ void k_stats(void)
{
    __shared__ float red[256];
    const int b = blockIdx.x >> 3, h = blockIdx.x & 7, tid = threadIdx.x;
    const float* L = g_logit + ((size_t)(b * NH + h)) * NN;
    float m = -1e30f;
    for (int n = tid; n < NN; n += 256) m = fmaxf(m, L[n]);
    red[tid] = m; __syncthreads();
    for (int s = 128; s > 0; s >>= 1) {
        if (tid < s) red[tid] = fmaxf(red[tid], red[tid + s]);
        __syncthreads();
    }
    m = red[0]; __syncthreads();
    float sum = 0.f;
    for (int n = tid; n < NN; n += 256) sum += expf(L[n] - m);
    red[tid] = sum; __syncthreads();
    for (int s = 128; s > 0; s >>= 1) {
        if (tid < s) red[tid] += red[tid + s];
        __syncthreads();
    }
    if (tid == 0) {
        g_ms[(b * NH + h) * 2] = m;
        g_ms[(b * NH + h) * 2 + 1] = 1.f / red[0];
    }
    if (tid < 64) g_G[b * TD + h * 64 + tid] = 0.f;
}

// ===========================================================================
// K2b: G accumulation.  grid 1024 (b x 128 chunks of 64 tokens), 256 threads
// ===========================================================================
__global__ void __launch_bounds__(256) k_accG(void)
{
    __shared__ float ws[8 * 64];
    __shared__ float ms[16];
    const int b = blockIdx.x >> 7, n0 = (blockIdx.x & 127) * 64, tid = threadIdx.x;
    if (tid < 16) ms[tid] = g_ms[b * 16 + tid];
    __syncthreads();
    for (int i = tid; i < 512; i += 256) {
        int h = i >> 6, t = i & 63;
        ws[i] = expf(g_logit[((size_t)(b * NH + h)) * NN + n0 + t] - ms[h * 2]) * ms[h * 2 + 1];
    }
    __syncthreads();
    const int d0 = tid, d1 = tid + 256;
    const int h0 = d0 >> 6, h1 = d1 >> 6;
    float a0 = 0.f, a1 = 0.f;
    const float* qb = g_q + ((size_t)b * NN + n0) * TD;
    #pragma unroll 4
    for (int t = 0; t < 64; ++t) {
        a0 += ws[h0 * 64 + t] * qb[(size_t)t * TD + d0];
        a1 += ws[h1 * 64 + t] * qb[(size_t)t * TD + d1];
    }
    atomicAdd(&g_G[b * TD + d0], a0);
    atomicAdd(&g_G[b * TD + d1], a1);
}

// ===========================================================================
// K3b: out = [U|q] @ Wc^T + bc  (M=128, N=64, K=1024). grid 512, 256 threads
// ===========================================================================
__global__ void __launch_bounds__(256, 2) k_out(float* __restrict__ out)
{
    extern __shared__ float sm[];
    float* Ah = sm;                    // [128][36]
    float* Bs = Ah + 128 * LDST;       // [64][36]

    const int tid  = threadIdx.x;
    const int wid  = tid >> 5, lane = tid & 31;
    const int grp  = lane >> 2, tig = lane & 3;
    const int bi   = blockIdx.x >> 6;
    const int t0   = (blockIdx.x & 63) << 7;

    float acc[8][4];
    #pragma unroll
    for (int nt = 0; nt < 8; ++nt)
        #pragma unroll
        for (int j = 0; j < 4; ++j) acc[nt][j] = 0.f;

    for (int kt = 0; kt < 32; ++kt) {
        const float* A = (kt < 16 ? g_u : g_q) + ((size_t)bi * NN + t0) * TD + (kt & 15) * 32;
        __syncthreads();
        #pragma unroll
        for (int i = 0; i < 4; ++i) {
            int e = tid + i * 256;
            int r = e >> 3, c4 = e & 7;
            float4 v = *(const float4*)(A + (size_t)r * TD + c4 * 4);
            v.x = tf32rn(v.x); v.y = tf32rn(v.y);
            v.z = tf32rn(v.z); v.w = tf32rn(v.w);
            *(float4*)(Ah + r * LDST + c4 * 4) = v;
        }
        #pragma unroll
        for (int i = 0; i < 2; ++i) {            // B chunk [64,32], pre-rounded
            int e = tid + i * 256;
            int r = e >> 3, c4 = e & 7;
            float4 v = *(const float4*)(g_wc + (size_t)r * 1024 + kt * 32 + c4 * 4);
            *(float4*)(Bs + r * LDST + c4 * 4) = v;
        }
        __syncthreads();

        #pragma unroll
        for (int ks = 0; ks < 4; ++ks) {
            const int kb = ks * 8;
            unsigned ah[4], bfr[8][2];
            const int r0 = wid * 16 + grp;
            ah[0] = __float_as_uint(Ah[r0 * LDST + kb + tig]);
            ah[1] = __float_as_uint(Ah[(r0 + 8) * LDST + kb + tig]);
            ah[2] = __float_as_uint(Ah[r0 * LDST + kb + tig + 4]);
            ah[3] = __float_as_uint(Ah[(r0 + 8) * LDST + kb + tig + 4]);
            #pragma unroll
            for (int nt = 0; nt < 8; ++nt) {
                const int c0 = nt * 8 + grp;
                bfr[nt][0] = __float_as_uint(Bs[c0 * LDST + kb + tig]);
                bfr[nt][1] = __float_as_uint(Bs[c0 * LDST + kb + tig + 4]);
            }
            #pragma unroll
            for (int nt = 0; nt < 8; ++nt)
                MMA8(acc[nt], ah, bfr[nt]);
        }
    }

    #pragma unroll
    for (int s = 0; s < 2; ++s) {
        const int row = wid * 16 + s * 8 + grp;
        const int token = t0 + row;
        float* orow = out + ((size_t)bi * NN + token) * 64;
        #pragma unroll
        for (int nt = 0; nt < 8; ++nt) {
            const int c = nt * 8 + tig * 2;
            float2 v = make_float2(acc[nt][s * 2] + g_bc[c],
                                   acc[nt][s * 2 + 1] + g_bc[c + 1]);
            *(float2*)(orow + c) = v;
        }
    }
}

// ===========================================================================
extern "C" void kernel_launch(void* const* d_in, const int* in_sizes, int n_in,
                              void* d_out, int out_size)
{
    (void)in_sizes; (void)n_in; (void)out_size;
    const float* x  = (const float*)d_in[0];
    const float* Wq = (const float*)d_in[1];
    const float* bq = (const float*)d_in[2];
    const float* Wk = (const float*)d_in[3];
    const float* bk = (const float*)d_in[4];
    const float* wg = (const float*)d_in[5];
    const float* Wp = (const float*)d_in[6];
    const float* bp = (const float*)d_in[7];
    const float* Wf = (const float*)d_in[8];
    const float* bf = (const float*)d_in[9];
    float* out = (float*)d_out;

    const int smem_proj = 2 * 128 * LDST * (int)sizeof(float);              // 36864
    const int smem_out  = (128 + 64) * LDST * (int)sizeof(float);           // 27648
    cudaFuncSetAttribute(k_proj, cudaFuncAttributeMaxDynamicSharedMemorySize, smem_proj);
    cudaFuncSetAttribute(k_out,  cudaFuncAttributeMaxDynamicSharedMemorySize, smem_out);

    k_wc<<<64, 512>>>(Wp, Wf, bp, bf);
    k_proj<<<2048, 256, smem_proj>>>(x, Wq, bq, wg, 0);
    k_stats<<<64, 256>>>();
    k_accG<<<1024, 256>>>();
    k_proj<<<2048, 256, smem_proj>>>(x, Wk, bk, wg, 1);
    k_out<<<512, 256, smem_out>>>(out);
}